// round 1
// baseline (speedup 1.0000x reference)
#include <cuda_runtime.h>
#include <cuda_bf16.h>
#include <math_constants.h>

// Problem constants (shapes fixed by the dataset)
#define NB      8192     // batch
#define ND      128      // embedding dim
#define TM      128      // tile rows
#define TN      128      // tile cols
#define STRIDE  132      // padded smem row stride (floats), 16B-aligned rows
#define MARGIN  1.0f

// -------- scratch in device globals (no allocation allowed) --------
__device__ unsigned int g_hardest[NB];   // float bits of hardest-negative distance (init +inf)
__device__ float        g_sq[NB];        // squared norms
__device__ int          g_labels[NB];    // labels as int32
__device__ float        g_total;
__device__ int          g_count;

// Detect whether the label buffer is int64 or int32 (JAX x64 off => int32).
// For int64 little-endian, every odd 32-bit word is the (zero) high half.
__device__ __forceinline__ int labels_are_64(const int* p) {
    int ok = 1;
    #pragma unroll
    for (int q = 0; q < 32; ++q) ok &= (p[2 * q + 1] == 0);
    return ok;
}

// ---------------- kernel 0: init (sq norms, labels, hardest=inf) ----------------
__global__ void __launch_bounds__(256) init_kernel(const float* __restrict__ E,
                                                   const void* __restrict__ labels_raw) {
    int warp = (blockIdx.x * blockDim.x + threadIdx.x) >> 5;
    int lane = threadIdx.x & 31;
    if (warp >= NB) return;

    float4 e = *(const float4*)(E + (size_t)warp * ND + lane * 4);
    float s = e.x * e.x + e.y * e.y + e.z * e.z + e.w * e.w;
    #pragma unroll
    for (int o = 16; o > 0; o >>= 1) s += __shfl_xor_sync(0xffffffffu, s, o);

    if (lane == 0) {
        g_sq[warp] = s;
        g_hardest[warp] = 0x7f800000u;  // +inf
        const int* p32 = (const int*)labels_raw;
        if (labels_are_64(p32)) {
            g_labels[warp] = (int)((const long long*)labels_raw)[warp];
        } else {
            g_labels[warp] = p32[warp];
        }
    }
    if (blockIdx.x == 0 && threadIdx.x == 0) { g_total = 0.0f; g_count = 0; }
}

// ---------------- kernel 1: tiled GEMM + fused masked row-min ----------------
// Grid (64, 64): block (jt, it) computes the 128x128 tile of E*E^T for rows
// it*128.., cols jt*128.., derives masked distances, reduces min per row,
// and atomicMin's into g_hardest (positive float bits are order-preserving).
extern __shared__ float smem1[];
__global__ void __launch_bounds__(256) pass1_kernel(const float* __restrict__ E) {
    float* As = smem1;                 // [128][STRIDE] transposed: As[k][m]
    float* Bs = smem1 + TM * STRIDE;   // [128][STRIDE] transposed: Bs[k][n]

    const int t  = threadIdx.x;        // 0..255
    const int w  = t >> 5;             // warp 0..7
    const int l  = t & 31;             // lane
    const int it = blockIdx.y, jt = blockIdx.x;

    const float* Arow = E + (size_t)it * TM * ND;
    const float* Brow = E + (size_t)jt * TM * ND;

    // Load both tiles transposed into smem. Lane dimension = row => STS
    // conflict-free (bank = row % 32). Global loads are 16B per lane at 512B
    // stride (50% sector use) — L2-resident, cheap.
    #pragma unroll
    for (int c = 0; c < 4; ++c) {
        int f4 = w * 4 + c;            // which float4 chunk of the row (0..31)
        #pragma unroll
        for (int q = 0; q < 4; ++q) {
            int row = q * 32 + l;
            float4 va = __ldg((const float4*)(Arow + (size_t)row * ND) + f4);
            float4 vb = __ldg((const float4*)(Brow + (size_t)row * ND) + f4);
            int k = f4 * 4;
            As[(k + 0) * STRIDE + row] = va.x;
            As[(k + 1) * STRIDE + row] = va.y;
            As[(k + 2) * STRIDE + row] = va.z;
            As[(k + 3) * STRIDE + row] = va.w;
            Bs[(k + 0) * STRIDE + row] = vb.x;
            Bs[(k + 1) * STRIDE + row] = vb.y;
            Bs[(k + 2) * STRIDE + row] = vb.z;
            Bs[(k + 3) * STRIDE + row] = vb.w;
        }
    }
    __syncthreads();

    const int tx = t & 15, ty = t >> 4;   // 16x16 thread grid
    // Micro-tile: rows {ty*4+0..3, 64+ty*4+0..3}, cols {tx*4+0..3, 64+tx*4+0..3}.
    // Split-by-64 makes the float4 smem reads contiguous across lanes => conflict-free.
    float acc[8][8];
    #pragma unroll
    for (int i = 0; i < 8; ++i)
        #pragma unroll
        for (int j = 0; j < 8; ++j) acc[i][j] = 0.0f;

    #pragma unroll 8
    for (int k = 0; k < 128; ++k) {
        float a[8], b[8];
        *(float4*)&a[0] = *(const float4*)&As[k * STRIDE + ty * 4];
        *(float4*)&a[4] = *(const float4*)&As[k * STRIDE + 64 + ty * 4];
        *(float4*)&b[0] = *(const float4*)&Bs[k * STRIDE + tx * 4];
        *(float4*)&b[4] = *(const float4*)&Bs[k * STRIDE + 64 + tx * 4];
        #pragma unroll
        for (int i = 0; i < 8; ++i)
            #pragma unroll
            for (int j = 0; j < 8; ++j) acc[i][j] = fmaf(a[i], b[j], acc[i][j]);
    }

    // Epilogue: masked min over this tile's columns for each of my 8 rows.
    int   rloc[8], cloc[8];
    float sqi[8], sqj[8];
    int   li[8], lj[8];
    #pragma unroll
    for (int u = 0; u < 8; ++u) {
        rloc[u] = (u < 4) ? (ty * 4 + u) : (64 + ty * 4 + (u - 4));
        cloc[u] = (u < 4) ? (tx * 4 + u) : (64 + tx * 4 + (u - 4));
        sqi[u] = g_sq[it * TM + rloc[u]];
        sqj[u] = g_sq[jt * TN + cloc[u]];
        li[u]  = g_labels[it * TM + rloc[u]];
        lj[u]  = g_labels[jt * TN + cloc[u]];
    }

    float rmin[8];
    #pragma unroll
    for (int u = 0; u < 8; ++u) rmin[u] = CUDART_INF_F;
    #pragma unroll
    for (int u = 0; u < 8; ++u) {
        #pragma unroll
        for (int v = 0; v < 8; ++v) {
            if (lj[v] != li[u]) {
                float d = fmaxf(sqi[u] + sqj[v] - 2.0f * acc[u][v], 0.0f);
                rmin[u] = fminf(rmin[u], d);
            }
        }
    }

    // Cross-thread (16 tx) min per row via smem, then atomicMin to global.
    __syncthreads();
    float* red = smem1;                  // reuse: [128][16]
    #pragma unroll
    for (int u = 0; u < 8; ++u) red[rloc[u] * 16 + tx] = rmin[u];
    __syncthreads();
    if (t < TM) {
        float m = CUDART_INF_F;
        #pragma unroll
        for (int x = 0; x < 16; ++x) m = fminf(m, red[t * 16 + x]);
        atomicMin(&g_hardest[it * TM + t], __float_as_uint(m));
    }
}

// ---------------- kernel 2: positives scan + loss accumulation ----------------
// One warp per anchor. Scan labels for matches, compute exact fp32 distance for
// each positive, test against hardest negative, accumulate.
__global__ void __launch_bounds__(256) pass2_kernel(const float* __restrict__ E) {
    int i    = (blockIdx.x * blockDim.x + threadIdx.x) >> 5;  // anchor
    int lane = threadIdx.x & 31;
    if (i >= NB) return;

    float4 e  = *(const float4*)(E + (size_t)i * ND + lane * 4);
    int   li  = g_labels[i];
    float sqi = g_sq[i];
    float hn  = __uint_as_float(g_hardest[i]);  // +inf if no negative => never valid

    float lsum = 0.0f;
    int   lcnt = 0;

    for (int jb = 0; jb < NB; jb += 32) {
        int j = jb + lane;
        int match = (g_labels[j] == li) && (j != i);
        unsigned m = __ballot_sync(0xffffffffu, match);
        while (m) {
            int b = __ffs(m) - 1;
            m &= m - 1;
            int p = jb + b;
            float4 f = *(const float4*)(E + (size_t)p * ND + lane * 4);
            float pd = e.x * f.x + e.y * f.y + e.z * f.z + e.w * f.w;
            #pragma unroll
            for (int o = 16; o > 0; o >>= 1) pd += __shfl_xor_sync(0xffffffffu, pd, o);
            float d = fmaxf(sqi + g_sq[p] - 2.0f * pd, 0.0f);
            if (lane == 0 && hn < d) {
                lsum += fmaxf(d - hn + MARGIN, 0.0f);
                lcnt += 1;
            }
        }
    }
    if (lane == 0) {
        if (lcnt) {
            atomicAdd(&g_total, lsum);
            atomicAdd(&g_count, lcnt);
        }
    }
}

// ---------------- kernel 3: finalize ----------------
__global__ void fin_kernel(float* out, int n) {
    int i = blockIdx.x * blockDim.x + threadIdx.x;
    if (i >= n) return;
    if (i == 0) {
        int c = g_count;
        out[0] = g_total / (float)(c > 0 ? c : 1);
    } else if (i == 1) {
        out[1] = (float)g_count;
    } else {
        out[i] = 0.0f;
    }
}

extern "C" void kernel_launch(void* const* d_in, const int* in_sizes, int n_in,
                              void* d_out, int out_size) {
    const float* E   = (const float*)d_in[0];
    const void*  lab = d_in[1];

    const int SMEM_BYTES = 2 * TM * STRIDE * (int)sizeof(float);  // 135168
    cudaFuncSetAttribute(pass1_kernel, cudaFuncAttributeMaxDynamicSharedMemorySize,
                         SMEM_BYTES);

    init_kernel<<<NB / 8, 256>>>(E, lab);
    pass1_kernel<<<dim3(NB / TN, NB / TM), 256, SMEM_BYTES>>>(E);
    pass2_kernel<<<NB / 8, 256>>>(E);
    int nthr = out_size < 1 ? 1 : out_size;
    fin_kernel<<<(nthr + 255) / 256, 256>>>((float*)d_out, out_size);
}

// round 2
// speedup vs baseline: 1.8427x; 1.8427x over previous
#include <cuda_runtime.h>
#include <cuda_bf16.h>
#include <math_constants.h>

// Problem constants (shapes fixed by the dataset)
#define NB      8192     // batch
#define ND      128      // embedding dim
#define TM      128      // tile rows
#define TN      128      // tile cols
#define STRIDE  132      // padded smem row stride (floats), 16B-aligned rows
#define MARGIN  1.0f
#define NT      (NB / TM)            // 64 tiles per dim
#define NTRI    (NT * (NT + 1) / 2)  // 2080 lower-triangle tiles

// -------- scratch in device globals (no allocation allowed) --------
__device__ unsigned int g_hardest[NB];   // float bits of hardest-negative distance (init +inf)
__device__ float        g_sq[NB];        // squared norms
__device__ int          g_labels[NB];    // labels as int32
__device__ float        g_total;
__device__ int          g_count;

// ---------- packed fp32x2 helpers (Blackwell FFMA2 path, PTX-only) ----------
__device__ __forceinline__ unsigned long long bcast2(float x) {
    unsigned long long r;
    asm("mov.b64 %0, {%1, %1};" : "=l"(r) : "f"(x));
    return r;
}
__device__ __forceinline__ unsigned long long pack2(float x, float y) {
    unsigned long long r;
    asm("mov.b64 %0, {%1, %2};" : "=l"(r) : "f"(x), "f"(y));
    return r;
}
__device__ __forceinline__ void ffma2(unsigned long long& d,
                                      unsigned long long a,
                                      unsigned long long b) {
    asm("fma.rn.f32x2 %0, %1, %2, %3;" : "=l"(d) : "l"(a), "l"(b), "l"(d));
}
__device__ __forceinline__ void unpack2(unsigned long long v, float& lo, float& hi) {
    asm("mov.b64 {%0, %1}, %2;" : "=f"(lo), "=f"(hi) : "l"(v));
}

// Detect whether the label buffer is int64 or int32 (JAX x64 off => int32).
// For int64 little-endian, every odd 32-bit word is the (zero) high half.
__device__ __forceinline__ int labels_are_64(const int* p) {
    int ok = 1;
    #pragma unroll
    for (int q = 0; q < 32; ++q) ok &= (p[2 * q + 1] == 0);
    return ok;
}

// ---------------- kernel 0: init (sq norms, labels, hardest=inf) ----------------
__global__ void __launch_bounds__(256) init_kernel(const float* __restrict__ E,
                                                   const void* __restrict__ labels_raw) {
    int warp = (blockIdx.x * blockDim.x + threadIdx.x) >> 5;
    int lane = threadIdx.x & 31;
    if (warp >= NB) return;

    float4 e = *(const float4*)(E + (size_t)warp * ND + lane * 4);
    float s = e.x * e.x + e.y * e.y + e.z * e.z + e.w * e.w;
    #pragma unroll
    for (int o = 16; o > 0; o >>= 1) s += __shfl_xor_sync(0xffffffffu, s, o);

    if (lane == 0) {
        g_sq[warp] = s;
        g_hardest[warp] = 0x7f800000u;  // +inf
        const int* p32 = (const int*)labels_raw;
        if (labels_are_64(p32)) {
            g_labels[warp] = (int)((const long long*)labels_raw)[warp];
        } else {
            g_labels[warp] = p32[warp];
        }
    }
    if (blockIdx.x == 0 && threadIdx.x == 0) { g_total = 0.0f; g_count = 0; }
}

// ---------------- kernel 1: triangular tiled GEMM + fused masked min ----------------
// One block per lower-triangle tile (it >= jt). Each tile's 128x128 distances
// feed BOTH the row anchors' masked min (over tile cols) and, by symmetry,
// the col anchors' masked min (over tile rows). atomicMin(float-bits) merge.
extern __shared__ float smem1[];
__global__ void __launch_bounds__(256) pass1_kernel(const float* __restrict__ E) {
    // --- decode triangular block index: b = it*(it+1)/2 + jt, jt <= it ---
    int b = blockIdx.x;
    int it = (int)((sqrtf(8.0f * (float)b + 1.0f) - 1.0f) * 0.5f);
    while ((it + 1) * (it + 2) / 2 <= b) ++it;
    while (it * (it + 1) / 2 > b) --it;
    int jt = b - it * (it + 1) / 2;

    float* As = smem1;                 // [128][STRIDE] transposed: As[k][m] (rows it*128..)
    float* Bs = smem1 + TM * STRIDE;   // [128][STRIDE] transposed: Bs[k][n] (rows jt*128..)

    const int t = threadIdx.x;         // 0..255
    const int w = t >> 5;              // warp 0..7
    const int l = t & 31;              // lane

    const float* Arow = E + (size_t)it * TM * ND;
    const float* Brow = E + (size_t)jt * TM * ND;

    #pragma unroll
    for (int c = 0; c < 4; ++c) {
        int f4 = w * 4 + c;            // which float4 chunk of the row (0..31)
        #pragma unroll
        for (int q = 0; q < 4; ++q) {
            int row = q * 32 + l;
            float4 va = __ldg((const float4*)(Arow + (size_t)row * ND) + f4);
            float4 vb = __ldg((const float4*)(Brow + (size_t)row * ND) + f4);
            int k = f4 * 4;
            As[(k + 0) * STRIDE + row] = va.x;
            As[(k + 1) * STRIDE + row] = va.y;
            As[(k + 2) * STRIDE + row] = va.z;
            As[(k + 3) * STRIDE + row] = va.w;
            Bs[(k + 0) * STRIDE + row] = vb.x;
            Bs[(k + 1) * STRIDE + row] = vb.y;
            Bs[(k + 2) * STRIDE + row] = vb.z;
            Bs[(k + 3) * STRIDE + row] = vb.w;
        }
    }
    __syncthreads();

    const int tx = t & 15, ty = t >> 4;   // 16x16 thread grid
    // Micro-tile rows {ty*4+0..3, 64+ty*4+0..3}, cols {tx*4+0..3, 64+tx*4+0..3}.
    // acc2[i][j] holds the packed pair of columns (2j, 2j+1) for row i.
    unsigned long long acc2[8][4];
    #pragma unroll
    for (int i = 0; i < 8; ++i)
        #pragma unroll
        for (int j = 0; j < 4; ++j) acc2[i][j] = 0ull;

    #pragma unroll 4
    for (int k = 0; k < 128; ++k) {
        float a[8], bv[8];
        *(float4*)&a[0]  = *(const float4*)&As[k * STRIDE + ty * 4];
        *(float4*)&a[4]  = *(const float4*)&As[k * STRIDE + 64 + ty * 4];
        *(float4*)&bv[0] = *(const float4*)&Bs[k * STRIDE + tx * 4];
        *(float4*)&bv[4] = *(const float4*)&Bs[k * STRIDE + 64 + tx * 4];
        unsigned long long bp[4];
        #pragma unroll
        for (int j = 0; j < 4; ++j) bp[j] = pack2(bv[2 * j], bv[2 * j + 1]);
        #pragma unroll
        for (int i = 0; i < 8; ++i) {
            unsigned long long ap = bcast2(a[i]);
            #pragma unroll
            for (int j = 0; j < 4; ++j) ffma2(acc2[i][j], ap, bp[j]);
        }
    }

    // --------- epilogue: masked row-min AND col-min over this tile ---------
    int   rloc[8], cloc[8];
    float sqi[8], sqj[8];
    int   li[8], lj[8];
    #pragma unroll
    for (int u = 0; u < 8; ++u) {
        rloc[u] = (u < 4) ? (ty * 4 + u) : (64 + ty * 4 + (u - 4));
        cloc[u] = (u < 4) ? (tx * 4 + u) : (64 + tx * 4 + (u - 4));
        sqi[u] = g_sq[it * TM + rloc[u]];
        sqj[u] = g_sq[jt * TN + cloc[u]];
        li[u]  = g_labels[it * TM + rloc[u]];
        lj[u]  = g_labels[jt * TN + cloc[u]];
    }

    float rmin[8], cmin[8];
    #pragma unroll
    for (int u = 0; u < 8; ++u) { rmin[u] = CUDART_INF_F; cmin[u] = CUDART_INF_F; }
    #pragma unroll
    for (int u = 0; u < 8; ++u) {
        #pragma unroll
        for (int j = 0; j < 4; ++j) {
            float d0, d1;
            unpack2(acc2[u][j], d0, d1);
            int v0 = 2 * j, v1 = 2 * j + 1;
            if (lj[v0] != li[u]) {
                float d = fmaxf(sqi[u] + sqj[v0] - 2.0f * d0, 0.0f);
                rmin[u]  = fminf(rmin[u], d);
                cmin[v0] = fminf(cmin[v0], d);
            }
            if (lj[v1] != li[u]) {
                float d = fmaxf(sqi[u] + sqj[v1] - 2.0f * d1, 0.0f);
                rmin[u]  = fminf(rmin[u], d);
                cmin[v1] = fminf(cmin[v1], d);
            }
        }
    }

    // Row pass: reduce over 16 tx, merge into anchors it*128 + r.
    __syncthreads();
    float* red = smem1;                  // reuse: [128][16]
    #pragma unroll
    for (int u = 0; u < 8; ++u) red[rloc[u] * 16 + tx] = rmin[u];
    __syncthreads();
    if (t < TM) {
        float m = CUDART_INF_F;
        #pragma unroll
        for (int x = 0; x < 16; ++x) m = fminf(m, red[t * 16 + x]);
        atomicMin(&g_hardest[it * TM + t], __float_as_uint(m));
    }
    // Col pass (symmetry): reduce over 16 ty, merge into anchors jt*128 + c.
    __syncthreads();
    #pragma unroll
    for (int u = 0; u < 8; ++u) red[cloc[u] * 16 + ty] = cmin[u];
    __syncthreads();
    if (t < TM) {
        float m = CUDART_INF_F;
        #pragma unroll
        for (int x = 0; x < 16; ++x) m = fminf(m, red[t * 16 + x]);
        atomicMin(&g_hardest[jt * TM + t], __float_as_uint(m));
    }
}

// ---------------- kernel 2: positives scan + loss accumulation ----------------
// One warp per anchor. Scan labels for matches, compute exact fp32 distance for
// each positive, test against hardest negative, accumulate.
__global__ void __launch_bounds__(256) pass2_kernel(const float* __restrict__ E) {
    int i    = (blockIdx.x * blockDim.x + threadIdx.x) >> 5;  // anchor
    int lane = threadIdx.x & 31;
    if (i >= NB) return;

    float4 e  = *(const float4*)(E + (size_t)i * ND + lane * 4);
    int   li  = g_labels[i];
    float sqi = g_sq[i];
    float hn  = __uint_as_float(g_hardest[i]);  // +inf if no negative => never valid

    float lsum = 0.0f;
    int   lcnt = 0;

    for (int jb = 0; jb < NB; jb += 32) {
        int j = jb + lane;
        int match = (g_labels[j] == li) && (j != i);
        unsigned m = __ballot_sync(0xffffffffu, match);
        while (m) {
            int b = __ffs(m) - 1;
            m &= m - 1;
            int p = jb + b;
            float4 f = *(const float4*)(E + (size_t)p * ND + lane * 4);
            float pd = e.x * f.x + e.y * f.y + e.z * f.z + e.w * f.w;
            #pragma unroll
            for (int o = 16; o > 0; o >>= 1) pd += __shfl_xor_sync(0xffffffffu, pd, o);
            float d = fmaxf(sqi + g_sq[p] - 2.0f * pd, 0.0f);
            if (lane == 0 && hn < d) {
                lsum += fmaxf(d - hn + MARGIN, 0.0f);
                lcnt += 1;
            }
        }
    }
    if (lane == 0) {
        if (lcnt) {
            atomicAdd(&g_total, lsum);
            atomicAdd(&g_count, lcnt);
        }
    }
}

// ---------------- kernel 3: finalize ----------------
__global__ void fin_kernel(float* out, int n) {
    int i = blockIdx.x * blockDim.x + threadIdx.x;
    if (i >= n) return;
    if (i == 0) {
        int c = g_count;
        out[0] = g_total / (float)(c > 0 ? c : 1);
    } else if (i == 1) {
        out[1] = (float)g_count;
    } else {
        out[i] = 0.0f;
    }
}

extern "C" void kernel_launch(void* const* d_in, const int* in_sizes, int n_in,
                              void* d_out, int out_size) {
    const float* E   = (const float*)d_in[0];
    const void*  lab = d_in[1];

    const int SMEM_BYTES = 2 * TM * STRIDE * (int)sizeof(float);  // 135168
    cudaFuncSetAttribute(pass1_kernel, cudaFuncAttributeMaxDynamicSharedMemorySize,
                         SMEM_BYTES);

    init_kernel<<<NB / 8, 256>>>(E, lab);
    pass1_kernel<<<NTRI, 256, SMEM_BYTES>>>(E);
    pass2_kernel<<<NB / 8, 256>>>(E);
    int nthr = out_size < 1 ? 1 : out_size;
    fin_kernel<<<(nthr + 255) / 256, 256>>>((float*)d_out, out_size);
}

// round 5
// speedup vs baseline: 3.4681x; 1.8821x over previous
#include <cuda_runtime.h>
#include <cuda_bf16.h>
#include <math_constants.h>
#include <cstdint>

#define NB      8192
#define ND      128
#define TM      128
#define MARGIN  1.0f
#define NT      (NB / TM)            // 64
#define NTRI    (NT * (NT + 1) / 2)  // 2080

// smem tile: 128 rows x 136 halves (272B padded rows -> conflict-free ldmatrix)
#define RSTRIDE 136
#define BUFB    (128 * RSTRIDE * 2)  // 34816 bytes per operand buffer

#define OFF_LI    0
#define OFF_LJ    512
#define OFF_SQI   1024
#define OFF_SQJ   1536
#define OFF_SCR_R 2048              // float [128][4]
#define OFF_SCR_C 4096              // float [128][2]
#define OFF_BUF   5120              // 4 x BUFB: A_b0, A_b1, B_b0, B_b1
#define SMEM_SZ   (OFF_BUF + 4 * BUFB)   // 144384

// -------- scratch in device globals (no allocation allowed) --------
__device__ unsigned int    g_hardest[NB];
__device__ float           g_sq[NB];
__device__ int             g_labels[NB];
__device__ float           g_total;
__device__ int             g_count;
__device__ __nv_bfloat16   g_eb0[NB * ND];   // bf16 high part
__device__ __nv_bfloat16   g_eb1[NB * ND];   // bf16 residual

__device__ __forceinline__ uint32_t smem_u32(const void* p) {
    uint32_t a;
    asm("{ .reg .u64 t; cvta.to.shared.u64 t, %1; cvt.u32.u64 %0, t; }" : "=r"(a) : "l"(p));
    return a;
}

__device__ __forceinline__ void ldm_x4(uint32_t* r, uint32_t addr) {
    asm volatile("ldmatrix.sync.aligned.m8n8.x4.shared.b16 {%0,%1,%2,%3}, [%4];"
                 : "=r"(r[0]), "=r"(r[1]), "=r"(r[2]), "=r"(r[3]) : "r"(addr));
}
__device__ __forceinline__ void mma_bf16(float* c, const uint32_t* a, uint32_t b0, uint32_t b1) {
    asm volatile(
        "mma.sync.aligned.m16n8k16.row.col.f32.bf16.bf16.f32 "
        "{%0,%1,%2,%3}, {%4,%5,%6,%7}, {%8,%9}, {%0,%1,%2,%3};"
        : "+f"(c[0]), "+f"(c[1]), "+f"(c[2]), "+f"(c[3])
        : "r"(a[0]), "r"(a[1]), "r"(a[2]), "r"(a[3]), "r"(b0), "r"(b1));
}

__device__ __forceinline__ int labels_are_64(const int* p) {
    int ok = 1;
    #pragma unroll
    for (int q = 0; q < 32; ++q) ok &= (p[2 * q + 1] == 0);
    return ok;
}

// ---------------- kernel 0: init (sq, labels, bf16 split, hardest=inf) ----------------
__global__ void __launch_bounds__(256) init_kernel(const float* __restrict__ E,
                                                   const void* __restrict__ labels_raw) {
    int warp = (blockIdx.x * blockDim.x + threadIdx.x) >> 5;
    int lane = threadIdx.x & 31;
    if (warp >= NB) return;

    float4 e = *(const float4*)(E + (size_t)warp * ND + lane * 4);
    float s = e.x * e.x + e.y * e.y + e.z * e.z + e.w * e.w;
    #pragma unroll
    for (int o = 16; o > 0; o >>= 1) s += __shfl_xor_sync(0xffffffffu, s, o);

    float xs[4] = {e.x, e.y, e.z, e.w};
    __nv_bfloat16 b0[4], b1[4];
    #pragma unroll
    for (int k = 0; k < 4; ++k) {
        b0[k] = __float2bfloat16(xs[k]);
        b1[k] = __float2bfloat16(xs[k] - __bfloat162float(b0[k]));
    }
    size_t base = (size_t)warp * ND + lane * 4;
    *(ushort4*)(g_eb0 + base) = *(ushort4*)b0;
    *(ushort4*)(g_eb1 + base) = *(ushort4*)b1;

    if (lane == 0) {
        g_sq[warp] = s;
        g_hardest[warp] = 0x7f800000u;  // +inf
        const int* p32 = (const int*)labels_raw;
        if (labels_are_64(p32)) {
            g_labels[warp] = (int)((const long long*)labels_raw)[warp];
        } else {
            g_labels[warp] = p32[warp];
        }
    }
    if (blockIdx.x == 0 && threadIdx.x == 0) { g_total = 0.0f; g_count = 0; }
}

// ---------------- kernel 1: triangular tile, HMMA bf16-split GEMM + masked min ----------------
extern __shared__ char smem_raw[];
__global__ void __launch_bounds__(256) pass1_kernel() {
    // decode triangular block index b = it*(it+1)/2 + jt, jt <= it
    int b = blockIdx.x;
    int it = (int)((sqrtf(8.0f * (float)b + 1.0f) - 1.0f) * 0.5f);
    while ((it + 1) * (it + 2) / 2 <= b) ++it;
    while (it * (it + 1) / 2 > b) --it;
    int jt = b - it * (it + 1) / 2;

    const int t    = threadIdx.x;
    const int wid  = t >> 5;
    const int lane = t & 31;
    const int wm   = wid >> 2;      // 0..1  (m half)
    const int wn   = wid & 3;       // 0..3  (n quarter)
    const int g    = lane >> 2;     // group in quad layout
    const int qt   = lane & 3;      // thread in quad
    uint32_t sbase = smem_u32(smem_raw);

    // header: labels + sq for tile rows/cols
    if (t < 128) {
        *(int*)  (smem_raw + OFF_LI  + t * 4) = g_labels[it * TM + t];
        *(float*)(smem_raw + OFF_SQI + t * 4) = g_sq[it * TM + t];
    } else {
        int c = t - 128;
        *(int*)  (smem_raw + OFF_LJ  + c * 4) = g_labels[jt * TM + c];
        *(float*)(smem_raw + OFF_SQJ + c * 4) = g_sq[jt * TM + c];
    }

    // fill 4 operand buffers: [A_b0, A_b1, B_b0, B_b1], padded 272B rows
    #pragma unroll
    for (int buf = 0; buf < 4; ++buf) {
        int mat = buf >> 1, s = buf & 1;
        const __nv_bfloat16* src =
            (s ? g_eb1 : g_eb0) + (size_t)((mat ? jt : it) * TM) * ND;
        char* dst = smem_raw + OFF_BUF + buf * BUFB;
        #pragma unroll
        for (int q = 0; q < 8; ++q) {
            int idx = t + q * 256;           // 2048 chunks of 16B
            int row = idx >> 4, c16 = idx & 15;
            uint4 v = *(const uint4*)((const char*)src + (size_t)row * 256 + c16 * 16);
            *(uint4*)(dst + row * (RSTRIDE * 2) + c16 * 16) = v;
        }
    }
    __syncthreads();

    // ldmatrix base addresses.
    // A: [m][k] rows, non-trans -> a-frag (m = g, k = qt*2..).
    // B: [n][k] rows, non-trans -> b-frag (n = g, k = qt*2..)  [col-major B == row-major B^T]
    uint32_t aA0 = sbase + OFF_BUF;
    uint32_t aB0 = sbase + OFF_BUF + 2 * BUFB;
    uint32_t aOffA = ((wm * 64 + (lane & 15)) * RSTRIDE + (lane >> 4) * 8) * 2;
    uint32_t aOffB = ((wn * 32 + ((lane >> 4) * 8) + (lane & 7)) * RSTRIDE +
                      ((lane >> 3) & 1) * 8) * 2;

    float acc[4][4][4];   // [mi][ni][c]
    #pragma unroll
    for (int mi = 0; mi < 4; ++mi)
        #pragma unroll
        for (int ni = 0; ni < 4; ++ni)
            #pragma unroll
            for (int c = 0; c < 4; ++c) acc[mi][ni][c] = 0.0f;

    #pragma unroll
    for (int pass = 0; pass < 3; ++pass) {
        // pass0: A_b0*B_b0; pass1: A_b0*B_b1; pass2: A_b1*B_b0
        const uint32_t pA = aA0 + (pass == 2 ? BUFB : 0) + aOffA;
        const uint32_t pB = aB0 + (pass == 1 ? BUFB : 0) + aOffB;
        #pragma unroll
        for (int ks = 0; ks < 8; ++ks) {
            uint32_t afr[4][4], bfr[2][4];
            #pragma unroll
            for (int mi = 0; mi < 4; ++mi)
                ldm_x4(afr[mi], pA + mi * (16 * RSTRIDE * 2) + ks * 32);
            #pragma unroll
            for (int np = 0; np < 2; ++np)
                ldm_x4(bfr[np], pB + np * (16 * RSTRIDE * 2) + ks * 32);
            #pragma unroll
            for (int mi = 0; mi < 4; ++mi)
                #pragma unroll
                for (int ni = 0; ni < 4; ++ni)
                    mma_bf16(acc[mi][ni], afr[mi],
                             bfr[ni >> 1][(ni & 1) * 2], bfr[ni >> 1][(ni & 1) * 2 + 1]);
        }
    }

    // ---------------- epilogue: masked row-min and col-min ----------------
    // C-frag: c0,c1 -> row (mi*16+g), cols (ni*8 + qt*2 +{0,1}); c2,c3 -> row +8.
    int   liR[4][2];  float sqiR[4][2];
    int   ljC[4][2];  float sqjC[4][2];
    #pragma unroll
    for (int mi = 0; mi < 4; ++mi)
        #pragma unroll
        for (int h = 0; h < 2; ++h) {
            int R = wm * 64 + mi * 16 + h * 8 + g;
            liR[mi][h]  = *(const int*)  (smem_raw + OFF_LI  + R * 4);
            sqiR[mi][h] = *(const float*)(smem_raw + OFF_SQI + R * 4);
        }
    #pragma unroll
    for (int ni = 0; ni < 4; ++ni)
        #pragma unroll
        for (int cb = 0; cb < 2; ++cb) {
            int C = wn * 32 + ni * 8 + qt * 2 + cb;
            ljC[ni][cb]  = *(const int*)  (smem_raw + OFF_LJ  + C * 4);
            sqjC[ni][cb] = *(const float*)(smem_raw + OFF_SQJ + C * 4);
        }

    float rowmin[4][2], colmin[4][2];
    #pragma unroll
    for (int x = 0; x < 4; ++x)
        #pragma unroll
        for (int y = 0; y < 2; ++y) { rowmin[x][y] = CUDART_INF_F; colmin[x][y] = CUDART_INF_F; }

    #pragma unroll
    for (int mi = 0; mi < 4; ++mi)
        #pragma unroll
        for (int ni = 0; ni < 4; ++ni)
            #pragma unroll
            for (int h = 0; h < 2; ++h)
                #pragma unroll
                for (int cb = 0; cb < 2; ++cb) {
                    float dot = acc[mi][ni][h * 2 + cb];
                    float d = fmaxf(fmaf(-2.0f, dot, sqiR[mi][h] + sqjC[ni][cb]), 0.0f);
                    float m = (ljC[ni][cb] != liR[mi][h]) ? d : CUDART_INF_F;
                    rowmin[mi][h]  = fminf(rowmin[mi][h], m);
                    colmin[ni][cb] = fminf(colmin[ni][cb], m);
                }

    // rows: reduce across quad (qt), lane qt==0 writes scratch_r[R][wn]
    #pragma unroll
    for (int mi = 0; mi < 4; ++mi)
        #pragma unroll
        for (int h = 0; h < 2; ++h) {
            float v = rowmin[mi][h];
            v = fminf(v, __shfl_xor_sync(0xffffffffu, v, 1));
            v = fminf(v, __shfl_xor_sync(0xffffffffu, v, 2));
            if (qt == 0) {
                int R = wm * 64 + mi * 16 + h * 8 + g;
                *(float*)(smem_raw + OFF_SCR_R + (R * 4 + wn) * 4) = v;
            }
        }
    // cols: reduce across groups (g), lanes 0..3 write scratch_c[C][wm]
    #pragma unroll
    for (int ni = 0; ni < 4; ++ni)
        #pragma unroll
        for (int cb = 0; cb < 2; ++cb) {
            float v = colmin[ni][cb];
            v = fminf(v, __shfl_xor_sync(0xffffffffu, v, 4));
            v = fminf(v, __shfl_xor_sync(0xffffffffu, v, 8));
            v = fminf(v, __shfl_xor_sync(0xffffffffu, v, 16));
            if (lane < 4) {
                int C = wn * 32 + ni * 8 + qt * 2 + cb;
                *(float*)(smem_raw + OFF_SCR_C + (C * 2 + wm) * 4) = v;
            }
        }
    __syncthreads();

    if (t < 128) {
        const float* sr = (const float*)(smem_raw + OFF_SCR_R) + t * 4;
        float m = fminf(fminf(sr[0], sr[1]), fminf(sr[2], sr[3]));
        atomicMin(&g_hardest[it * TM + t], __float_as_uint(m));
    } else {
        int c = t - 128;
        const float* sc = (const float*)(smem_raw + OFF_SCR_C) + c * 2;
        float m = fminf(sc[0], sc[1]);
        atomicMin(&g_hardest[jt * TM + c], __float_as_uint(m));
    }
}

// ---------------- kernel 2: positives scan + loss accumulation ----------------
__global__ void __launch_bounds__(256) pass2_kernel(const float* __restrict__ E) {
    int i    = (blockIdx.x * blockDim.x + threadIdx.x) >> 5;
    int lane = threadIdx.x & 31;
    if (i >= NB) return;

    float4 e  = *(const float4*)(E + (size_t)i * ND + lane * 4);
    int   li  = g_labels[i];
    float sqi = g_sq[i];
    float hn  = __uint_as_float(g_hardest[i]);

    float lsum = 0.0f;
    int   lcnt = 0;

    for (int jb = 0; jb < NB; jb += 32) {
        int j = jb + lane;
        int match = (g_labels[j] == li) && (j != i);
        unsigned m = __ballot_sync(0xffffffffu, match);
        while (m) {
            int bb = __ffs(m) - 1;
            m &= m - 1;
            int p = jb + bb;
            float4 f = *(const float4*)(E + (size_t)p * ND + lane * 4);
            float pd = e.x * f.x + e.y * f.y + e.z * f.z + e.w * f.w;
            #pragma unroll
            for (int o = 16; o > 0; o >>= 1) pd += __shfl_xor_sync(0xffffffffu, pd, o);
            float d = fmaxf(sqi + g_sq[p] - 2.0f * pd, 0.0f);
            if (lane == 0 && hn < d) {
                lsum += fmaxf(d - hn + MARGIN, 0.0f);
                lcnt += 1;
            }
        }
    }
    if (lane == 0 && lcnt) {
        atomicAdd(&g_total, lsum);
        atomicAdd(&g_count, lcnt);
    }
}

// ---------------- kernel 3: finalize ----------------
__global__ void fin_kernel(float* out, int n) {
    int i = blockIdx.x * blockDim.x + threadIdx.x;
    if (i >= n) return;
    if (i == 0) {
        int c = g_count;
        out[0] = g_total / (float)(c > 0 ? c : 1);
    } else if (i == 1) {
        out[1] = (float)g_count;
    } else {
        out[i] = 0.0f;
    }
}

extern "C" void kernel_launch(void* const* d_in, const int* in_sizes, int n_in,
                              void* d_out, int out_size) {
    const float* E   = (const float*)d_in[0];
    const void*  lab = d_in[1];

    cudaFuncSetAttribute(pass1_kernel, cudaFuncAttributeMaxDynamicSharedMemorySize, SMEM_SZ);

    init_kernel<<<NB / 8, 256>>>(E, lab);
    pass1_kernel<<<NTRI, 256, SMEM_SZ>>>();
    pass2_kernel<<<NB / 8, 256>>>(E);
    int nthr = out_size < 1 ? 1 : out_size;
    fin_kernel<<<(nthr + 255) / 256, 256>>>((float*)d_out, out_size);
}

// round 7
// speedup vs baseline: 8.1931x; 2.3624x over previous
#include <cuda_runtime.h>
#include <cuda_bf16.h>
#include <math_constants.h>
#include <cstdint>

#define NB      8192
#define ND      128
#define TM      128
#define MARGIN  1.0f
#define NT      (NB / TM)            // 64
#define NTRI    (NT * (NT + 1) / 2)  // 2080
#define NCLS    1024

// smem tile: 128 rows x 136 halves (272B padded rows -> conflict-free ldmatrix)
#define RSTRIDE 136
#define BUFB    (128 * RSTRIDE * 2)  // 34816 bytes per operand buffer

#define OFF_LI    0
#define OFF_LJ    512
#define OFF_SQI   1024
#define OFF_SQJ   1536
#define OFF_SCR_R 2048              // float [128][4]
#define OFF_SCR_C 4096              // float [128][2]
#define OFF_BUF   5120              // 2 x BUFB: A_h0, B_h0
#define SMEM_SZ   (OFF_BUF + 2 * BUFB)   // 74752 -> 2 CTAs/SM

// -------- scratch in device globals (no allocation allowed) --------
__device__ unsigned int g_hardest[NB];
__device__ float        g_sq[NB];
__device__ int          g_labels[NB];
__device__ float        g_total;
__device__ int          g_count;
__device__ __nv_bfloat16 g_eb[NB * ND];  // bf16 embeddings
__device__ int          g_off[NCLS + 1]; // bucket offsets
__device__ int          g_cur[NCLS];     // scatter cursors
__device__ int          g_members[NB];   // bucket members

__device__ __forceinline__ uint32_t smem_u32(const void* p) {
    uint32_t a;
    asm("{ .reg .u64 t; cvta.to.shared.u64 t, %1; cvt.u32.u64 %0, t; }" : "=r"(a) : "l"(p));
    return a;
}
__device__ __forceinline__ void ldm_x4(uint32_t* r, uint32_t addr) {
    asm volatile("ldmatrix.sync.aligned.m8n8.x4.shared.b16 {%0,%1,%2,%3}, [%4];"
                 : "=r"(r[0]), "=r"(r[1]), "=r"(r[2]), "=r"(r[3]) : "r"(addr));
}
__device__ __forceinline__ void mma_bf16(float* c, const uint32_t* a, uint32_t b0, uint32_t b1) {
    asm volatile(
        "mma.sync.aligned.m16n8k16.row.col.f32.bf16.bf16.f32 "
        "{%0,%1,%2,%3}, {%4,%5,%6,%7}, {%8,%9}, {%0,%1,%2,%3};"
        : "+f"(c[0]), "+f"(c[1]), "+f"(c[2]), "+f"(c[3])
        : "r"(a[0]), "r"(a[1]), "r"(a[2]), "r"(a[3]), "r"(b0), "r"(b1));
}
__device__ __forceinline__ int labels_are_64(const int* p) {
    int ok = 1;
    #pragma unroll
    for (int q = 0; q < 32; ++q) ok &= (p[2 * q + 1] == 0);
    return ok;
}

// ---------------- kernel 0: init (sq, labels, bf16 convert, hardest=inf) ----------------
__global__ void __launch_bounds__(256) init_kernel(const float* __restrict__ E,
                                                   const void* __restrict__ labels_raw) {
    int warp = (blockIdx.x * blockDim.x + threadIdx.x) >> 5;
    int lane = threadIdx.x & 31;
    if (warp >= NB) return;

    float4 e = *(const float4*)(E + (size_t)warp * ND + lane * 4);
    float s = e.x * e.x + e.y * e.y + e.z * e.z + e.w * e.w;
    #pragma unroll
    for (int o = 16; o > 0; o >>= 1) s += __shfl_xor_sync(0xffffffffu, s, o);

    __nv_bfloat16 b0[4] = {__float2bfloat16(e.x), __float2bfloat16(e.y),
                           __float2bfloat16(e.z), __float2bfloat16(e.w)};
    *(ushort4*)(g_eb + (size_t)warp * ND + lane * 4) = *(ushort4*)b0;

    if (lane == 0) {
        g_sq[warp] = s;
        g_hardest[warp] = 0x7f800000u;  // +inf
        const int* p32 = (const int*)labels_raw;
        if (labels_are_64(p32)) {
            g_labels[warp] = (int)((const long long*)labels_raw)[warp];
        } else {
            g_labels[warp] = p32[warp];
        }
    }
    if (blockIdx.x == 0 && threadIdx.x == 0) { g_total = 0.0f; g_count = 0; }
}

// ---------------- kernel 0b: histogram + scan (single block) ----------------
__global__ void __launch_bounds__(1024) scan_kernel() {
    __shared__ int h[NCLS];
    __shared__ int sc[NCLS];
    int t = threadIdx.x;
    h[t] = 0;
    __syncthreads();
    for (int i = t; i < NB; i += 1024) atomicAdd(&h[g_labels[i]], 1);
    __syncthreads();
    int v = h[t];
    sc[t] = v;
    __syncthreads();
    for (int off = 1; off < 1024; off <<= 1) {
        int x = (t >= off) ? sc[t - off] : 0;
        __syncthreads();
        sc[t] += x;
        __syncthreads();
    }
    int excl = sc[t] - v;
    g_off[t] = excl;
    g_cur[t] = excl;
    if (t == 0) g_off[NCLS] = NB;
}

// ---------------- kernel 0c: scatter members into buckets ----------------
__global__ void __launch_bounds__(256) scatter_kernel() {
    int i = blockIdx.x * blockDim.x + threadIdx.x;
    if (i >= NB) return;
    int pos = atomicAdd(&g_cur[g_labels[i]], 1);
    g_members[pos] = i;
}

// ---------------- kernel 1: triangular tile, 1-pass bf16 HMMA + masked min ----------------
extern __shared__ char smem_raw[];
__global__ void __launch_bounds__(256, 2) pass1_kernel() {
    // decode triangular block index b = it*(it+1)/2 + jt, jt <= it
    int b = blockIdx.x;
    int it = (int)((sqrtf(8.0f * (float)b + 1.0f) - 1.0f) * 0.5f);
    while ((it + 1) * (it + 2) / 2 <= b) ++it;
    while (it * (it + 1) / 2 > b) --it;
    int jt = b - it * (it + 1) / 2;

    const int t    = threadIdx.x;
    const int wid  = t >> 5;
    const int lane = t & 31;
    const int wm   = wid >> 2;      // 0..1  (m half)
    const int wn   = wid & 3;       // 0..3  (n quarter)
    const int g    = lane >> 2;     // group
    const int qt   = lane & 3;      // thread in quad
    uint32_t sbase = smem_u32(smem_raw);

    if (t < 128) {
        *(int*)  (smem_raw + OFF_LI  + t * 4) = g_labels[it * TM + t];
        *(float*)(smem_raw + OFF_SQI + t * 4) = g_sq[it * TM + t];
    } else {
        int c = t - 128;
        *(int*)  (smem_raw + OFF_LJ  + c * 4) = g_labels[jt * TM + c];
        *(float*)(smem_raw + OFF_SQJ + c * 4) = g_sq[jt * TM + c];
    }

    // fill 2 operand buffers: [A (rows it*128..), B (rows jt*128..)], 272B padded rows
    #pragma unroll
    for (int buf = 0; buf < 2; ++buf) {
        const __nv_bfloat16* src = g_eb + (size_t)((buf ? jt : it) * TM) * ND;
        char* dst = smem_raw + OFF_BUF + buf * BUFB;
        #pragma unroll
        for (int q = 0; q < 8; ++q) {
            int idx = t + q * 256;           // 2048 chunks of 16B
            int row = idx >> 4, c16 = idx & 15;
            uint4 v = *(const uint4*)((const char*)src + (size_t)row * 256 + c16 * 16);
            *(uint4*)(dst + row * (RSTRIDE * 2) + c16 * 16) = v;
        }
    }
    __syncthreads();

    // ldmatrix addressing (proven layout from R5)
    uint32_t pA = sbase + OFF_BUF +
                  ((wm * 64 + (lane & 15)) * RSTRIDE + (lane >> 4) * 8) * 2;
    uint32_t pB = sbase + OFF_BUF + BUFB +
                  ((wn * 32 + ((lane >> 4) * 8) + (lane & 7)) * RSTRIDE +
                   ((lane >> 3) & 1) * 8) * 2;

    float acc[4][4][4];   // [mi][ni][c]
    #pragma unroll
    for (int mi = 0; mi < 4; ++mi)
        #pragma unroll
        for (int ni = 0; ni < 4; ++ni)
            #pragma unroll
            for (int c = 0; c < 4; ++c) acc[mi][ni][c] = 0.0f;

    #pragma unroll
    for (int ks = 0; ks < 8; ++ks) {
        uint32_t afr[4][4], bfr[2][4];
        #pragma unroll
        for (int mi = 0; mi < 4; ++mi)
            ldm_x4(afr[mi], pA + mi * (16 * RSTRIDE * 2) + ks * 32);
        #pragma unroll
        for (int np = 0; np < 2; ++np)
            ldm_x4(bfr[np], pB + np * (16 * RSTRIDE * 2) + ks * 32);
        #pragma unroll
        for (int mi = 0; mi < 4; ++mi)
            #pragma unroll
            for (int ni = 0; ni < 4; ++ni)
                mma_bf16(acc[mi][ni], afr[mi],
                         bfr[ni >> 1][(ni & 1) * 2], bfr[ni >> 1][(ni & 1) * 2 + 1]);
    }

    // ---------------- epilogue: masked row-min and col-min ----------------
    int   liR[4][2];  float sqiR[4][2];
    int   ljC[4][2];  float sqjC[4][2];
    #pragma unroll
    for (int mi = 0; mi < 4; ++mi)
        #pragma unroll
        for (int h = 0; h < 2; ++h) {
            int R = wm * 64 + mi * 16 + h * 8 + g;
            liR[mi][h]  = *(const int*)  (smem_raw + OFF_LI  + R * 4);
            sqiR[mi][h] = *(const float*)(smem_raw + OFF_SQI + R * 4);
        }
    #pragma unroll
    for (int ni = 0; ni < 4; ++ni)
        #pragma unroll
        for (int cb = 0; cb < 2; ++cb) {
            int C = wn * 32 + ni * 8 + qt * 2 + cb;
            ljC[ni][cb]  = *(const int*)  (smem_raw + OFF_LJ  + C * 4);
            sqjC[ni][cb] = *(const float*)(smem_raw + OFF_SQJ + C * 4);
        }

    float rowmin[4][2], colmin[4][2];
    #pragma unroll
    for (int x = 0; x < 4; ++x)
        #pragma unroll
        for (int y = 0; y < 2; ++y) { rowmin[x][y] = CUDART_INF_F; colmin[x][y] = CUDART_INF_F; }

    #pragma unroll
    for (int mi = 0; mi < 4; ++mi)
        #pragma unroll
        for (int ni = 0; ni < 4; ++ni)
            #pragma unroll
            for (int h = 0; h < 2; ++h)
                #pragma unroll
                for (int cb = 0; cb < 2; ++cb) {
                    float dot = acc[mi][ni][h * 2 + cb];
                    float d = fmaxf(fmaf(-2.0f, dot, sqiR[mi][h] + sqjC[ni][cb]), 0.0f);
                    float m = (ljC[ni][cb] != liR[mi][h]) ? d : CUDART_INF_F;
                    rowmin[mi][h]  = fminf(rowmin[mi][h], m);
                    colmin[ni][cb] = fminf(colmin[ni][cb], m);
                }

    #pragma unroll
    for (int mi = 0; mi < 4; ++mi)
        #pragma unroll
        for (int h = 0; h < 2; ++h) {
            float v = rowmin[mi][h];
            v = fminf(v, __shfl_xor_sync(0xffffffffu, v, 1));
            v = fminf(v, __shfl_xor_sync(0xffffffffu, v, 2));
            if (qt == 0) {
                int R = wm * 64 + mi * 16 + h * 8 + g;
                *(float*)(smem_raw + OFF_SCR_R + (R * 4 + wn) * 4) = v;
            }
        }
    #pragma unroll
    for (int ni = 0; ni < 4; ++ni)
        #pragma unroll
        for (int cb = 0; cb < 2; ++cb) {
            float v = colmin[ni][cb];
            v = fminf(v, __shfl_xor_sync(0xffffffffu, v, 4));
            v = fminf(v, __shfl_xor_sync(0xffffffffu, v, 8));
            v = fminf(v, __shfl_xor_sync(0xffffffffu, v, 16));
            if (lane < 4) {
                int C = wn * 32 + ni * 8 + qt * 2 + cb;
                *(float*)(smem_raw + OFF_SCR_C + (C * 2 + wm) * 4) = v;
            }
        }
    __syncthreads();

    if (t < 128) {
        const float* sr = (const float*)(smem_raw + OFF_SCR_R) + t * 4;
        float m = fminf(fminf(sr[0], sr[1]), fminf(sr[2], sr[3]));
        atomicMin(&g_hardest[it * TM + t], __float_as_uint(m));
    } else {
        int c = t - 128;
        const float* sc = (const float*)(smem_raw + OFF_SCR_C) + c * 2;
        float m = fminf(sc[0], sc[1]);
        atomicMin(&g_hardest[jt * TM + c], __float_as_uint(m));
    }
}

// ---------------- kernel 2: bucketed positives + loss accumulation ----------------
__global__ void __launch_bounds__(256) pass2_kernel(const float* __restrict__ E) {
    int i    = (blockIdx.x * blockDim.x + threadIdx.x) >> 5;
    int lane = threadIdx.x & 31;
    if (i >= NB) return;

    float4 e  = *(const float4*)(E + (size_t)i * ND + lane * 4);
    int   li  = g_labels[i];
    float sqi = g_sq[i];
    float hn  = __uint_as_float(g_hardest[i]);  // +inf => no negative => never valid

    int s = g_off[li], epos = g_off[li + 1];
    float lsum = 0.0f;
    int   lcnt = 0;

    for (int idx = s; idx < epos; ++idx) {
        int p = g_members[idx];              // broadcast load
        if (p == i) continue;
        float4 f = *(const float4*)(E + (size_t)p * ND + lane * 4);
        float pd = e.x * f.x + e.y * f.y + e.z * f.z + e.w * f.w;
        #pragma unroll
        for (int o = 16; o > 0; o >>= 1) pd += __shfl_xor_sync(0xffffffffu, pd, o);
        float d = fmaxf(sqi + g_sq[p] - 2.0f * pd, 0.0f);
        if (lane == 0 && hn < d) {
            lsum += fmaxf(d - hn + MARGIN, 0.0f);
            lcnt += 1;
        }
    }
    if (lane == 0 && lcnt) {
        atomicAdd(&g_total, lsum);
        atomicAdd(&g_count, lcnt);
    }
}

// ---------------- kernel 3: finalize ----------------
__global__ void fin_kernel(float* out, int n) {
    int i = blockIdx.x * blockDim.x + threadIdx.x;
    if (i >= n) return;
    if (i == 0) {
        int c = g_count;
        out[0] = g_total / (float)(c > 0 ? c : 1);
    } else if (i == 1) {
        out[1] = (float)g_count;
    } else {
        out[i] = 0.0f;
    }
}

extern "C" void kernel_launch(void* const* d_in, const int* in_sizes, int n_in,
                              void* d_out, int out_size) {
    const float* E   = (const float*)d_in[0];
    const void*  lab = d_in[1];

    cudaFuncSetAttribute(pass1_kernel, cudaFuncAttributeMaxDynamicSharedMemorySize, SMEM_SZ);

    init_kernel<<<NB / 8, 256>>>(E, lab);
    scan_kernel<<<1, 1024>>>();
    scatter_kernel<<<NB / 256, 256>>>();
    pass1_kernel<<<NTRI, 256, SMEM_SZ>>>();
    pass2_kernel<<<NB / 8, 256>>>(E);
    int nthr = out_size < 1 ? 1 : out_size;
    fin_kernel<<<(nthr + 255) / 256, 256>>>((float*)d_out, out_size);
}